// round 2
// baseline (speedup 1.0000x reference)
#include <cuda_runtime.h>
#include <math.h>

// ---------------- problem constants ----------------
static constexpr int B_   = 32;
static constexpr int CCH  = 3;
static constexpr int IMG  = 224;
static constexpr int P_   = 16;
static constexpr int GRD  = IMG / P_;        // 14
static constexpr int NP   = GRD * GRD;       // 196
static constexpr int NTOK = NP + 1;          // 197
static constexpr int H_   = 768;
static constexpr int NH   = 12;
static constexpr int HD   = 64;
static constexpr int MLP_ = 3072;
static constexpr int L_   = 12;
static constexpr int ROWS = B_ * NTOK;       // 6304
static constexpr int PROWS = B_ * NP;        // 6272

// ---------------- device scratch ----------------
__device__ float g_h   [ROWS * H_];
__device__ float g_y   [ROWS * H_];
__device__ float g_qkv [ROWS * 3 * H_];
__device__ float g_attn[ROWS * H_];
__device__ float g_mlp [ROWS * MLP_];
__device__ float g_tmp [PROWS * H_];

// ---------------- helpers ----------------
__device__ __forceinline__ float gelu_exact(float x) {
    return 0.5f * x * (1.0f + erff(x * 0.70710678118654752f));
}

// ---------------- SGEMM: C[M,N] = A[M,K] @ B[K,N] (+epilogue) ----------------
// EPI: 0 = store, 1 = +bias, 2 = +bias,gelu, 3 = +bias,gelu,+=C, 4 = +=C
template<int EPI>
__global__ void sgemm_kernel(const float* __restrict__ A, const float* __restrict__ Bm,
                             const float* __restrict__ bias, float* __restrict__ C,
                             int M, int N, int K) {
    constexpr int BM = 128, BN = 128, BK = 8, TM = 8, TN = 8;
    __shared__ float As[BK][BM];
    __shared__ float Bs[BK][BN];
    const int tid = threadIdx.x;            // 256 threads
    const int tx = tid % 16, ty = tid / 16;
    const int bx = blockIdx.x, by = blockIdx.y;

    float acc[TM][TN];
    #pragma unroll
    for (int i = 0; i < TM; i++)
        #pragma unroll
        for (int j = 0; j < TN; j++) acc[i][j] = 0.f;

    const int arow = tid >> 1;              // 0..127
    const int acol = (tid & 1) * 4;         // 0 or 4
    const int brow = tid >> 5;              // 0..7
    const int bcol = (tid & 31) * 4;        // 0..124

    const int gArow = by * BM + arow;
    const bool aValid = gArow < M;
    const float* Aptr = A + (long)gArow * K;
    const float* Bptr = Bm + (long)bx * BN;

    for (int k0 = 0; k0 < K; k0 += BK) {
        float4 av = aValid ? *(const float4*)(Aptr + k0 + acol) : make_float4(0.f,0.f,0.f,0.f);
        float4 bv = *(const float4*)(Bptr + (long)(k0 + brow) * N + bcol);
        As[acol+0][arow] = av.x;
        As[acol+1][arow] = av.y;
        As[acol+2][arow] = av.z;
        As[acol+3][arow] = av.w;
        *(float4*)&Bs[brow][bcol] = bv;
        __syncthreads();
        #pragma unroll
        for (int k = 0; k < BK; k++) {
            float ar[TM], br[TN];
            #pragma unroll
            for (int i = 0; i < TM; i++) ar[i] = As[k][ty*TM+i];
            #pragma unroll
            for (int j = 0; j < TN; j++) br[j] = Bs[k][tx*TN+j];
            #pragma unroll
            for (int i = 0; i < TM; i++)
                #pragma unroll
                for (int j = 0; j < TN; j++)
                    acc[i][j] += ar[i] * br[j];
        }
        __syncthreads();
    }

    const int crow0 = by * BM + ty * TM;
    const int ccol0 = bx * BN + tx * TN;
    for (int i = 0; i < TM; i++) {
        int r = crow0 + i;
        if (r >= M) break;
        float* cp = C + (long)r * N + ccol0;
        #pragma unroll
        for (int j = 0; j < TN; j++) {
            float v = acc[i][j];
            if (EPI == 1 || EPI == 2 || EPI == 3) v += bias[ccol0 + j];
            if (EPI == 2 || EPI == 3) v = gelu_exact(v);
            if (EPI == 3 || EPI == 4) v += cp[j];
            cp[j] = v;
        }
    }
}

// ---------------- LayerNorm over last dim (768), one block per row ----------------
__global__ void ln_kernel(const float* __restrict__ in, float* __restrict__ out,
                          const float* __restrict__ g, const float* __restrict__ b) {
    const int row = blockIdx.x;
    const int tid = threadIdx.x;  // 256
    const float* x = in + (long)row * H_;
    float v0 = x[tid], v1 = x[tid+256], v2 = x[tid+512];
    __shared__ float red[256];
    __shared__ float s_mean, s_rstd;
    red[tid] = v0 + v1 + v2;
    __syncthreads();
    for (int o = 128; o > 0; o >>= 1) { if (tid < o) red[tid] += red[tid+o]; __syncthreads(); }
    if (tid == 0) s_mean = red[0] * (1.f / H_);
    __syncthreads();
    float m = s_mean;
    float d0 = v0 - m, d1 = v1 - m, d2 = v2 - m;
    red[tid] = d0*d0 + d1*d1 + d2*d2;
    __syncthreads();
    for (int o = 128; o > 0; o >>= 1) { if (tid < o) red[tid] += red[tid+o]; __syncthreads(); }
    if (tid == 0) s_rstd = rsqrtf(red[0] * (1.f / H_) + 1e-5f);
    __syncthreads();
    float rs = s_rstd;
    float* o_ = out + (long)row * H_;
    o_[tid]     = d0 * rs * g[tid]     + b[tid];
    o_[tid+256] = d1 * rs * g[tid+256] + b[tid+256];
    o_[tid+512] = d2 * rs * g[tid+512] + b[tid+512];
}

// ---------------- patchify + LN(pn1) ----------------
__global__ void patchify_ln_kernel(const float* __restrict__ x,
                                   const float* __restrict__ g, const float* __restrict__ b,
                                   float* __restrict__ out) {
    const int pidx = blockIdx.x;              // 0..B*NP-1
    const int bimg = pidx / NP;
    const int pp   = pidx % NP;
    const int hg = pp / GRD, wg = pp % GRD;
    const int tid = threadIdx.x;              // 256
    float v[3];
    #pragma unroll
    for (int r = 0; r < 3; r++) {
        int f = tid + r * 256;                // feature = p1*48 + p2*3 + c
        int p1 = f / 48, rem = f % 48, p2 = rem / 3, c = rem % 3;
        v[r] = x[(((long)bimg*CCH + c)*IMG + (hg*P_ + p1))*IMG + (wg*P_ + p2)];
    }
    __shared__ float red[256];
    __shared__ float s_mean, s_rstd;
    red[tid] = v[0] + v[1] + v[2];
    __syncthreads();
    for (int o = 128; o > 0; o >>= 1) { if (tid < o) red[tid] += red[tid+o]; __syncthreads(); }
    if (tid == 0) s_mean = red[0] * (1.f / H_);
    __syncthreads();
    float m = s_mean;
    float d0 = v[0]-m, d1 = v[1]-m, d2 = v[2]-m;
    red[tid] = d0*d0 + d1*d1 + d2*d2;
    __syncthreads();
    for (int o = 128; o > 0; o >>= 1) { if (tid < o) red[tid] += red[tid+o]; __syncthreads(); }
    if (tid == 0) s_rstd = rsqrtf(red[0] * (1.f / H_) + 1e-5f);
    __syncthreads();
    float rs = s_rstd;
    float* o_ = out + (long)pidx * H_;
    o_[tid]     = d0 * rs * g[tid]     + b[tid];
    o_[tid+256] = d1 * rs * g[tid+256] + b[tid+256];
    o_[tid+512] = d2 * rs * g[tid+512] + b[tid+512];
}

// ---------------- LN(pn2) + cls + pos embed -> h ----------------
__global__ void assemble_kernel(const float* __restrict__ pemb,   // [B*NP, H] post patch-GEMM
                                const float* __restrict__ g, const float* __restrict__ b,
                                const float* __restrict__ cls, const float* __restrict__ pos,
                                float* __restrict__ h) {
    const int row = blockIdx.x;               // 0..B*NTOK-1
    const int bb = row / NTOK, t = row % NTOK;
    const int tid = threadIdx.x;
    float* o_ = h + (long)row * H_;
    if (t == 0) {
        o_[tid]     = cls[tid]     + pos[tid];
        o_[tid+256] = cls[tid+256] + pos[tid+256];
        o_[tid+512] = cls[tid+512] + pos[tid+512];
        return;
    }
    const float* x = pemb + (long)(bb*NP + t - 1) * H_;
    float v0 = x[tid], v1 = x[tid+256], v2 = x[tid+512];
    __shared__ float red[256];
    __shared__ float s_mean, s_rstd;
    red[tid] = v0 + v1 + v2;
    __syncthreads();
    for (int o = 128; o > 0; o >>= 1) { if (tid < o) red[tid] += red[tid+o]; __syncthreads(); }
    if (tid == 0) s_mean = red[0] * (1.f / H_);
    __syncthreads();
    float m = s_mean;
    float d0 = v0-m, d1 = v1-m, d2 = v2-m;
    red[tid] = d0*d0 + d1*d1 + d2*d2;
    __syncthreads();
    for (int o = 128; o > 0; o >>= 1) { if (tid < o) red[tid] += red[tid+o]; __syncthreads(); }
    if (tid == 0) s_rstd = rsqrtf(red[0] * (1.f / H_) + 1e-5f);
    __syncthreads();
    float rs = s_rstd;
    const float* pp = pos + (long)t * H_;
    o_[tid]     = d0 * rs * g[tid]     + b[tid]     + pp[tid];
    o_[tid+256] = d1 * rs * g[tid+256] + b[tid+256] + pp[tid+256];
    o_[tid+512] = d2 * rs * g[tid+512] + b[tid+512] + pp[tid+512];
}

// ---------------- attention: one block per (batch, head) ----------------
static constexpr int KSTR = HD + 1;           // 65, conflict-free d-major reads
static constexpr int ATTN_SMEM_FLOATS = NTOK*KSTR + NTOK*HD + 8*224 + 8*HD;
static constexpr int ATTN_SMEM_BYTES  = ATTN_SMEM_FLOATS * 4;  // ~110.9 KB

__global__ void attn_kernel(const float* __restrict__ qkv, float* __restrict__ attn_out) {
    extern __shared__ float sm[];
    float* Ks    = sm;                        // [NTOK][65]
    float* Vs    = Ks + NTOK*KSTR;            // [NTOK][64]
    float* Srows = Vs + NTOK*HD;              // 8 warps x 224
    float* Qrows = Srows + 8*224;             // 8 warps x 64

    const int bh = blockIdx.x;
    const int bb = bh / NH, head = bh % NH;
    const int tid = threadIdx.x, lane = tid & 31, warp = tid >> 5;
    const float* base = qkv + (long)bb * NTOK * 3 * H_;
    const int hoff = head * HD;

    for (int idx = tid; idx < NTOK * HD; idx += 256) {
        int j = idx / HD, d = idx % HD;
        const float* r = base + (long)j * 3 * H_;
        Ks[j*KSTR + d] = r[H_   + hoff + d];
        Vs[j*HD   + d] = r[2*H_ + hoff + d];
    }
    __syncthreads();

    float* srow = Srows + warp * 224;
    float* qrow = Qrows + warp * HD;

    for (int i = warp; i < NTOK; i += 8) {
        const float* qr = base + (long)i * 3 * H_ + hoff;
        qrow[lane]      = qr[lane];
        qrow[lane + 32] = qr[lane + 32];
        __syncwarp();
        float lmax = -1e30f;
        for (int j = lane; j < NTOK; j += 32) {
            float dot = 0.f;
            #pragma unroll
            for (int d = 0; d < HD; d++) dot += qrow[d] * Ks[j*KSTR + d];
            dot *= 0.125f;                    // 1/sqrt(64)
            srow[j] = dot;
            lmax = fmaxf(lmax, dot);
        }
        #pragma unroll
        for (int o = 16; o > 0; o >>= 1) lmax = fmaxf(lmax, __shfl_xor_sync(0xffffffffu, lmax, o));
        __syncwarp();
        float lsum = 0.f;
        for (int j = lane; j < NTOK; j += 32) {
            float e = __expf(srow[j] - lmax);
            srow[j] = e;
            lsum += e;
        }
        #pragma unroll
        for (int o = 16; o > 0; o >>= 1) lsum += __shfl_xor_sync(0xffffffffu, lsum, o);
        float inv = 1.f / lsum;
        __syncwarp();
        float acc0 = 0.f, acc1 = 0.f;
        for (int j = 0; j < NTOK; j++) {
            float w = srow[j];
            acc0 += w * Vs[j*HD + lane];
            acc1 += w * Vs[j*HD + lane + 32];
        }
        float* op = attn_out + (long)(bb*NTOK + i) * H_ + hoff;
        op[lane]      = acc0 * inv;
        op[lane + 32] = acc1 * inv;
        __syncwarp();
    }
}

// ---------------- mean pool over tokens ----------------
__global__ void meanpool_kernel(const float* __restrict__ h, float* __restrict__ out) {
    const int bb = blockIdx.x;
    const int j = threadIdx.x;   // 768
    float s = 0.f;
    for (int i = 0; i < NTOK; i++) s += h[((long)bb*NTOK + i) * H_ + j];
    out[bb*H_ + j] = s * (1.f / NTOK);
}

// ---------------- host orchestration ----------------
static inline dim3 gemm_grid(int M, int N) { return dim3((N + 127) / 128, (M + 127) / 128); }

extern "C" void kernel_launch(void* const* d_in, const int* in_sizes, int n_in,
                              void* d_out, int out_size) {
    const float* x      = (const float*)d_in[0];
    const float* pn1_g  = (const float*)d_in[1];
    const float* pn1_b  = (const float*)d_in[2];
    const float* pW     = (const float*)d_in[3];
    const float* pb     = (const float*)d_in[4];
    const float* pn2_g  = (const float*)d_in[5];
    const float* pn2_b  = (const float*)d_in[6];
    const float* cls    = (const float*)d_in[7];
    const float* pos    = (const float*)d_in[8];
    const float* ln1_g  = (const float*)d_in[9];
    const float* ln1_b  = (const float*)d_in[10];
    const float* qkv_W  = (const float*)d_in[11];
    const float* out_W  = (const float*)d_in[12];
    const float* ln2_g  = (const float*)d_in[13];
    const float* ln2_b  = (const float*)d_in[14];
    const float* fc1_W  = (const float*)d_in[15];
    const float* fc1_b  = (const float*)d_in[16];
    const float* fc2_W  = (const float*)d_in[17];
    const float* fc2_b  = (const float*)d_in[18];
    float* out = (float*)d_out;

    float *p_h, *p_y, *p_qkv, *p_attn, *p_mlp, *p_tmp;
    cudaGetSymbolAddress((void**)&p_h,    g_h);
    cudaGetSymbolAddress((void**)&p_y,    g_y);
    cudaGetSymbolAddress((void**)&p_qkv,  g_qkv);
    cudaGetSymbolAddress((void**)&p_attn, g_attn);
    cudaGetSymbolAddress((void**)&p_mlp,  g_mlp);
    cudaGetSymbolAddress((void**)&p_tmp,  g_tmp);

    cudaFuncSetAttribute(attn_kernel, cudaFuncAttributeMaxDynamicSharedMemorySize, ATTN_SMEM_BYTES);

    // 1) patchify + LN(pn1) -> g_y [B*NP, 768]
    patchify_ln_kernel<<<PROWS, 256>>>(x, pn1_g, pn1_b, p_y);

    // 2) patch embed GEMM + bias -> g_tmp
    sgemm_kernel<1><<<gemm_grid(PROWS, H_), 256>>>(p_y, pW, pb, p_tmp, PROWS, H_, H_);

    // 3) LN(pn2) + cls + pos -> g_h [B*NTOK, 768]
    assemble_kernel<<<ROWS, 256>>>(p_tmp, pn2_g, pn2_b, cls, pos, p_h);

    // 4) transformer layers
    for (int l = 0; l < L_; l++) {
        const float* l1g = ln1_g + l*H_;
        const float* l1b = ln1_b + l*H_;
        const float* qW  = qkv_W + (long)l*H_*3*H_;
        const float* oW  = out_W + (long)l*H_*H_;
        const float* l2g = ln2_g + l*H_;
        const float* l2b = ln2_b + l*H_;
        const float* f1W = fc1_W + (long)l*H_*MLP_;
        const float* f1b = fc1_b + (long)l*MLP_;
        const float* f2W = fc2_W + (long)l*MLP_*H_;
        const float* f2b = fc2_b + (long)l*H_;

        ln_kernel<<<ROWS, 256>>>(p_h, p_y, l1g, l1b);
        sgemm_kernel<0><<<gemm_grid(ROWS, 3*H_), 256>>>(p_y, qW, nullptr, p_qkv, ROWS, 3*H_, H_);
        attn_kernel<<<B_*NH, 256, ATTN_SMEM_BYTES>>>(p_qkv, p_attn);
        sgemm_kernel<4><<<gemm_grid(ROWS, H_), 256>>>(p_attn, oW, nullptr, p_h, ROWS, H_, H_);
        ln_kernel<<<ROWS, 256>>>(p_h, p_y, l2g, l2b);
        sgemm_kernel<2><<<gemm_grid(ROWS, MLP_), 256>>>(p_y, f1W, f1b, p_mlp, ROWS, MLP_, H_);
        sgemm_kernel<3><<<gemm_grid(ROWS, H_), 256>>>(p_mlp, f2W, f2b, p_h, ROWS, H_, MLP_);
    }

    // 5) mean pool -> out [B, H]
    meanpool_kernel<<<B_, H_>>>(p_h, out);
}

// round 4
// speedup vs baseline: 2.6616x; 2.6616x over previous
#include <cuda_runtime.h>
#include <cuda_bf16.h>
#include <math.h>
#include <cstdint>

// ---------------- problem constants ----------------
static constexpr int B_   = 32;
static constexpr int CCH  = 3;
static constexpr int IMG  = 224;
static constexpr int P_   = 16;
static constexpr int GRD  = IMG / P_;        // 14
static constexpr int NP   = GRD * GRD;       // 196
static constexpr int NTOK = NP + 1;          // 197
static constexpr int H_   = 768;
static constexpr int NH   = 12;
static constexpr int HD   = 64;
static constexpr int MLP_ = 3072;
static constexpr int L_   = 12;
static constexpr int ROWS = B_ * NTOK;       // 6304
static constexpr int PROWS = B_ * NP;        // 6272

// weight scratch layout (bf16 hi/lo, transposed to [N,K])
static constexpr long W_PATCH_OFF = 0;                       // 768x768
static constexpr long W_LAYER_BASE = 768L * 768;
static constexpr long W_LAYER_SZ   = 768L*2304 + 768L*768 + 768L*3072 + 3072L*768;
static constexpr long W_QKV_OFF = 0;
static constexpr long W_OUT_OFF = 768L*2304;
static constexpr long W_FC1_OFF = W_OUT_OFF + 768L*768;
static constexpr long W_FC2_OFF = W_FC1_OFF + 768L*3072;
static constexpr long W_TOTAL = W_LAYER_BASE + 12L * W_LAYER_SZ;

// ---------------- device scratch ----------------
__device__ float g_h   [ROWS * H_];
__device__ float g_qkv [ROWS * 3 * H_];
__device__ float g_tmp [PROWS * H_];
__device__ __align__(256) __nv_bfloat16 g_yh [ROWS * H_];
__device__ __align__(256) __nv_bfloat16 g_yl [ROWS * H_];
__device__ __align__(256) __nv_bfloat16 g_ah [ROWS * H_];
__device__ __align__(256) __nv_bfloat16 g_al [ROWS * H_];
__device__ __align__(256) __nv_bfloat16 g_mh [ROWS * MLP_];
__device__ __align__(256) __nv_bfloat16 g_ml [ROWS * MLP_];
__device__ __align__(256) __nv_bfloat16 g_wh [W_TOTAL];
__device__ __align__(256) __nv_bfloat16 g_wl [W_TOTAL];

// ---------------- helpers ----------------
__device__ __forceinline__ uint32_t smem_u32(const void* p) {
    uint32_t a;
    asm("{ .reg .u64 t; cvta.to.shared.u64 t, %1; cvt.u32.u64 %0, t; }" : "=r"(a) : "l"(p));
    return a;
}
__device__ __forceinline__ void cp16(uint32_t dst, const void* src, bool valid) {
    int sz = valid ? 16 : 0;
    asm volatile("cp.async.cg.shared.global [%0], [%1], 16, %2;"
                 :: "r"(dst), "l"(src), "r"(sz) : "memory");
}
__device__ __forceinline__ void cp_commit() {
    asm volatile("cp.async.commit_group;" ::: "memory");
}
__device__ __forceinline__ void cp_wait1() {
    asm volatile("cp.async.wait_group 1;" ::: "memory");
}
__device__ __forceinline__ void ldm4(uint32_t* r, uint32_t addr) {
    asm volatile("ldmatrix.sync.aligned.m8n8.x4.shared.b16 {%0,%1,%2,%3}, [%4];"
                 : "=r"(r[0]), "=r"(r[1]), "=r"(r[2]), "=r"(r[3]) : "r"(addr));
}
__device__ __forceinline__ void mma_bf16(float* d, const uint32_t* a, uint32_t b0, uint32_t b1) {
    asm volatile(
        "mma.sync.aligned.m16n8k16.row.col.f32.bf16.bf16.f32 "
        "{%0,%1,%2,%3}, {%4,%5,%6,%7}, {%8,%9}, {%0,%1,%2,%3};"
        : "+f"(d[0]), "+f"(d[1]), "+f"(d[2]), "+f"(d[3])
        : "r"(a[0]), "r"(a[1]), "r"(a[2]), "r"(a[3]), "r"(b0), "r"(b1));
}
__device__ __forceinline__ float gelu_exact(float x) {
    return 0.5f * x * (1.0f + erff(x * 0.70710678118654752f));
}

// ---------------- weight split+transpose: W[K,N] f32 -> Wh/Wl[N,K] bf16 ----------------
__global__ void wsplit_kernel(const float* __restrict__ W, __nv_bfloat16* __restrict__ Wh,
                              __nv_bfloat16* __restrict__ Wl, int K, int N) {
    __shared__ float t[32][33];
    const int n0 = blockIdx.x * 32, k0 = blockIdx.y * 32;
    const int tx = threadIdx.x, ty = threadIdx.y;    // 32 x 8
    #pragma unroll
    for (int i = 0; i < 32; i += 8)
        t[ty + i][tx] = W[(long)(k0 + ty + i) * N + n0 + tx];
    __syncthreads();
    #pragma unroll
    for (int i = 0; i < 32; i += 8) {
        float v = t[tx][ty + i];
        long o = (long)(n0 + ty + i) * K + k0 + tx;
        __nv_bfloat16 h = __float2bfloat16(v);
        Wh[o] = h;
        Wl[o] = __float2bfloat16(v - __bfloat162float(h));
    }
}

// ---------------- tensor-core GEMM via mma.sync (bf16 hi/lo split) ----------------
// C[M,N] = (Ah+Al)[M,K] @ (Wh+Wl)^T[N,K], fp32 accum.
// EPI: 0 store f32 | 1 +bias f32 | 2 +bias,gelu -> bf16 hi/lo | 3 +bias,gelu,+=C | 4 +=C
static constexpr int MG_STAGE = 32768;            // 4 tiles x 8KB
static constexpr int MG_SMEM  = 3 * MG_STAGE;     // 98304

template<int EPI>
__global__ void __launch_bounds__(256) mgemm_kernel(
    const __nv_bfloat16* __restrict__ Ah, const __nv_bfloat16* __restrict__ Al,
    const __nv_bfloat16* __restrict__ Wh, const __nv_bfloat16* __restrict__ Wl,
    const float* __restrict__ bias, float* __restrict__ C,
    __nv_bfloat16* __restrict__ Oh, __nv_bfloat16* __restrict__ Ol,
    int M, int N, int K)
{
    extern __shared__ char smc[];
    const uint32_t smb = smem_u32(smc);
    const int tid = threadIdx.x;
    const int lane = tid & 31, warp = tid >> 5;
    const int wm = warp >> 1, wn = warp & 1;      // 4 x 2 warp grid
    const int n0 = blockIdx.x * 128, m0 = blockIdx.y * 128;
    const int KT = K >> 5;

    float acc[2][8][4];
    #pragma unroll
    for (int a = 0; a < 2; a++)
        #pragma unroll
        for (int b = 0; b < 8; b++)
            #pragma unroll
            for (int c = 0; c < 4; c++) acc[a][b][c] = 0.f;

    auto issue = [&](int kt, int s) {
        const int k0 = kt << 5;
        const uint32_t st = smb + s * MG_STAGE;
        #pragma unroll
        for (int i = 0; i < 2; i++) {
            int idx = tid + (i << 8);
            int row = idx >> 2, ch = idx & 3;
            uint32_t off = (uint32_t)(row * 64 + ((ch ^ ((row >> 1) & 3)) << 4));
            bool av = (m0 + row) < M;
            long aoff = (long)(m0 + row) * K + k0 + ch * 8;
            long boff = (long)(n0 + row) * K + k0 + ch * 8;
            cp16(st +      0 + off, Ah + aoff, av);
            cp16(st +  8192 + off, Al + aoff, av);
            cp16(st + 16384 + off, Wh + boff, true);
            cp16(st + 24576 + off, Wl + boff, true);
        }
    };
    auto ldaddr = [&](uint32_t tb, int r0, int ks) -> uint32_t {
        int row = r0 + (lane & 7) + ((lane & 8) ? 8 : 0);
        int ch  = (ks << 1) + ((lane >> 4) & 1);
        return tb + (uint32_t)(row * 64 + ((ch ^ ((row >> 1) & 3)) << 4));
    };

    issue(0, 0);
    cp_commit();
    if (KT > 1) issue(1, 1);
    cp_commit();

    for (int kt = 0; kt < KT; kt++) {
        cp_wait1();
        __syncthreads();
        int pf = kt + 2;
        if (pf < KT) issue(pf, pf % 3);
        cp_commit();

        const uint32_t st = smb + (kt % 3) * MG_STAGE;
        #pragma unroll
        for (int ks = 0; ks < 2; ks++) {
            uint32_t ah[2][4], al[2][4], bh[4][4], bl[4][4];
            #pragma unroll
            for (int mt = 0; mt < 2; mt++) {
                ldm4(ah[mt], ldaddr(st +    0, wm * 32 + mt * 16, ks));
                ldm4(al[mt], ldaddr(st + 8192, wm * 32 + mt * 16, ks));
            }
            #pragma unroll
            for (int g = 0; g < 4; g++) {
                ldm4(bh[g], ldaddr(st + 16384, wn * 64 + g * 16, ks));
                ldm4(bl[g], ldaddr(st + 24576, wn * 64 + g * 16, ks));
            }
            #pragma unroll
            for (int mt = 0; mt < 2; mt++)
                #pragma unroll
                for (int nt = 0; nt < 8; nt++) {
                    int g = nt >> 1, sl = nt & 1;
                    mma_bf16(acc[mt][nt], ah[mt], bh[g][sl], bh[g][sl + 2]);
                    mma_bf16(acc[mt][nt], ah[mt], bl[g][sl], bl[g][sl + 2]);
                    mma_bf16(acc[mt][nt], al[mt], bh[g][sl], bh[g][sl + 2]);
                }
        }
    }

    // epilogue
    #pragma unroll
    for (int mt = 0; mt < 2; mt++)
        #pragma unroll
        for (int nt = 0; nt < 8; nt++) {
            int cb = n0 + wn * 64 + nt * 8 + (lane & 3) * 2;
            #pragma unroll
            for (int h = 0; h < 2; h++) {
                int r = m0 + wm * 32 + mt * 16 + (lane >> 2) + h * 8;
                if (r < M) {
                    float v0 = acc[mt][nt][h * 2 + 0];
                    float v1 = acc[mt][nt][h * 2 + 1];
                    if (EPI == 1 || EPI == 2 || EPI == 3) { v0 += bias[cb]; v1 += bias[cb + 1]; }
                    if (EPI == 2 || EPI == 3) { v0 = gelu_exact(v0); v1 = gelu_exact(v1); }
                    if (EPI == 2) {
                        long o = (long)r * N + cb;
                        __nv_bfloat16 h0 = __float2bfloat16(v0);
                        __nv_bfloat16 h1 = __float2bfloat16(v1);
                        Oh[o] = h0;      Ol[o] = __float2bfloat16(v0 - __bfloat162float(h0));
                        Oh[o + 1] = h1;  Ol[o + 1] = __float2bfloat16(v1 - __bfloat162float(h1));
                    } else {
                        float* cp = C + (long)r * N + cb;
                        if (EPI == 3 || EPI == 4) { v0 += cp[0]; v1 += cp[1]; }
                        cp[0] = v0; cp[1] = v1;
                    }
                }
            }
        }
}

// ---------------- LayerNorm (768) -> bf16 hi/lo ----------------
__global__ void ln_kernel(const float* __restrict__ in, __nv_bfloat16* __restrict__ yh,
                          __nv_bfloat16* __restrict__ yl,
                          const float* __restrict__ g, const float* __restrict__ b) {
    const int row = blockIdx.x;
    const int tid = threadIdx.x;  // 256
    const float* x = in + (long)row * H_;
    float v0 = x[tid], v1 = x[tid + 256], v2 = x[tid + 512];
    __shared__ float red[256];
    __shared__ float s_mean, s_rstd;
    red[tid] = v0 + v1 + v2;
    __syncthreads();
    for (int o = 128; o > 0; o >>= 1) { if (tid < o) red[tid] += red[tid + o]; __syncthreads(); }
    if (tid == 0) s_mean = red[0] * (1.f / H_);
    __syncthreads();
    float m = s_mean;
    float d0 = v0 - m, d1 = v1 - m, d2 = v2 - m;
    red[tid] = d0 * d0 + d1 * d1 + d2 * d2;
    __syncthreads();
    for (int o = 128; o > 0; o >>= 1) { if (tid < o) red[tid] += red[tid + o]; __syncthreads(); }
    if (tid == 0) s_rstd = rsqrtf(red[0] * (1.f / H_) + 1e-5f);
    __syncthreads();
    float rs = s_rstd;
    long base = (long)row * H_;
    #pragma unroll
    for (int rr = 0; rr < 3; rr++) {
        int c = tid + rr * 256;
        float d = (rr == 0 ? d0 : rr == 1 ? d1 : d2);
        float v = d * rs * g[c] + b[c];
        __nv_bfloat16 h = __float2bfloat16(v);
        yh[base + c] = h;
        yl[base + c] = __float2bfloat16(v - __bfloat162float(h));
    }
}

// ---------------- patchify + LN(pn1) -> bf16 hi/lo ----------------
__global__ void patchify_ln_kernel(const float* __restrict__ x,
                                   const float* __restrict__ g, const float* __restrict__ b,
                                   __nv_bfloat16* __restrict__ yh, __nv_bfloat16* __restrict__ yl) {
    const int pidx = blockIdx.x;
    const int bimg = pidx / NP;
    const int pp   = pidx % NP;
    const int hg = pp / GRD, wg = pp % GRD;
    const int tid = threadIdx.x;
    float v[3];
    #pragma unroll
    for (int r = 0; r < 3; r++) {
        int f = tid + r * 256;
        int p1 = f / 48, rem = f % 48, p2 = rem / 3, c = rem % 3;
        v[r] = x[(((long)bimg * CCH + c) * IMG + (hg * P_ + p1)) * IMG + (wg * P_ + p2)];
    }
    __shared__ float red[256];
    __shared__ float s_mean, s_rstd;
    red[tid] = v[0] + v[1] + v[2];
    __syncthreads();
    for (int o = 128; o > 0; o >>= 1) { if (tid < o) red[tid] += red[tid + o]; __syncthreads(); }
    if (tid == 0) s_mean = red[0] * (1.f / H_);
    __syncthreads();
    float m = s_mean;
    float d0 = v[0] - m, d1 = v[1] - m, d2 = v[2] - m;
    red[tid] = d0 * d0 + d1 * d1 + d2 * d2;
    __syncthreads();
    for (int o = 128; o > 0; o >>= 1) { if (tid < o) red[tid] += red[tid + o]; __syncthreads(); }
    if (tid == 0) s_rstd = rsqrtf(red[0] * (1.f / H_) + 1e-5f);
    __syncthreads();
    float rs = s_rstd;
    long base = (long)pidx * H_;
    #pragma unroll
    for (int rr = 0; rr < 3; rr++) {
        int c = tid + rr * 256;
        float d = (rr == 0 ? d0 : rr == 1 ? d1 : d2);
        float vv = d * rs * g[c] + b[c];
        __nv_bfloat16 h = __float2bfloat16(vv);
        yh[base + c] = h;
        yl[base + c] = __float2bfloat16(vv - __bfloat162float(h));
    }
}

// ---------------- LN(pn2) + cls + pos -> h (f32) ----------------
__global__ void assemble_kernel(const float* __restrict__ pemb,
                                const float* __restrict__ g, const float* __restrict__ b,
                                const float* __restrict__ cls, const float* __restrict__ pos,
                                float* __restrict__ h) {
    const int row = blockIdx.x;
    const int bb = row / NTOK, t = row % NTOK;
    const int tid = threadIdx.x;
    float* o_ = h + (long)row * H_;
    if (t == 0) {
        o_[tid]       = cls[tid]       + pos[tid];
        o_[tid + 256] = cls[tid + 256] + pos[tid + 256];
        o_[tid + 512] = cls[tid + 512] + pos[tid + 512];
        return;
    }
    const float* x = pemb + (long)(bb * NP + t - 1) * H_;
    float v0 = x[tid], v1 = x[tid + 256], v2 = x[tid + 512];
    __shared__ float red[256];
    __shared__ float s_mean, s_rstd;
    red[tid] = v0 + v1 + v2;
    __syncthreads();
    for (int o = 128; o > 0; o >>= 1) { if (tid < o) red[tid] += red[tid + o]; __syncthreads(); }
    if (tid == 0) s_mean = red[0] * (1.f / H_);
    __syncthreads();
    float m = s_mean;
    float d0 = v0 - m, d1 = v1 - m, d2 = v2 - m;
    red[tid] = d0 * d0 + d1 * d1 + d2 * d2;
    __syncthreads();
    for (int o = 128; o > 0; o >>= 1) { if (tid < o) red[tid] += red[tid + o]; __syncthreads(); }
    if (tid == 0) s_rstd = rsqrtf(red[0] * (1.f / H_) + 1e-5f);
    __syncthreads();
    float rs = s_rstd;
    const float* pp = pos + (long)t * H_;
    o_[tid]       = d0 * rs * g[tid]       + b[tid]       + pp[tid];
    o_[tid + 256] = d1 * rs * g[tid + 256] + b[tid + 256] + pp[tid + 256];
    o_[tid + 512] = d2 * rs * g[tid + 512] + b[tid + 512] + pp[tid + 512];
}

// ---------------- attention: one block per (batch, head); out bf16 hi/lo ----------------
static constexpr int KSTR = HD + 1;           // 65
static constexpr int ATTN_SMEM_FLOATS = NTOK * KSTR + NTOK * HD + 8 * 224 + 8 * HD;
static constexpr int ATTN_SMEM_BYTES  = ATTN_SMEM_FLOATS * 4;

__global__ void attn_kernel(const float* __restrict__ qkv,
                            __nv_bfloat16* __restrict__ oh, __nv_bfloat16* __restrict__ ol) {
    extern __shared__ float smf[];
    float* Ks    = smf;
    float* Vs    = Ks + NTOK * KSTR;
    float* Srows = Vs + NTOK * HD;
    float* Qrows = Srows + 8 * 224;

    const int bh = blockIdx.x;
    const int bb = bh / NH, head = bh % NH;
    const int tid = threadIdx.x, lane = tid & 31, warp = tid >> 5;
    const float* base = qkv + (long)bb * NTOK * 3 * H_;
    const int hoff = head * HD;

    for (int idx = tid; idx < NTOK * HD; idx += 256) {
        int j = idx / HD, d = idx % HD;
        const float* r = base + (long)j * 3 * H_;
        Ks[j * KSTR + d] = r[H_ + hoff + d];
        Vs[j * HD + d]   = r[2 * H_ + hoff + d];
    }
    __syncthreads();

    float* srow = Srows + warp * 224;
    float* qrow = Qrows + warp * HD;

    for (int i = warp; i < NTOK; i += 8) {
        const float* qr = base + (long)i * 3 * H_ + hoff;
        qrow[lane]      = qr[lane];
        qrow[lane + 32] = qr[lane + 32];
        __syncwarp();
        float lmax = -1e30f;
        for (int j = lane; j < NTOK; j += 32) {
            float dot = 0.f;
            #pragma unroll
            for (int d = 0; d < HD; d++) dot += qrow[d] * Ks[j * KSTR + d];
            dot *= 0.125f;
            srow[j] = dot;
            lmax = fmaxf(lmax, dot);
        }
        #pragma unroll
        for (int o = 16; o > 0; o >>= 1) lmax = fmaxf(lmax, __shfl_xor_sync(0xffffffffu, lmax, o));
        __syncwarp();
        float lsum = 0.f;
        for (int j = lane; j < NTOK; j += 32) {
            float e = __expf(srow[j] - lmax);
            srow[j] = e;
            lsum += e;
        }
        #pragma unroll
        for (int o = 16; o > 0; o >>= 1) lsum += __shfl_xor_sync(0xffffffffu, lsum, o);
        float inv = 1.f / lsum;
        __syncwarp();
        float acc0 = 0.f, acc1 = 0.f;
        for (int j = 0; j < NTOK; j++) {
            float w = srow[j];
            acc0 += w * Vs[j * HD + lane];
            acc1 += w * Vs[j * HD + lane + 32];
        }
        acc0 *= inv; acc1 *= inv;
        long ob = (long)(bb * NTOK + i) * H_ + hoff;
        __nv_bfloat16 h0 = __float2bfloat16(acc0);
        __nv_bfloat16 h1 = __float2bfloat16(acc1);
        oh[ob + lane]      = h0;
        ol[ob + lane]      = __float2bfloat16(acc0 - __bfloat162float(h0));
        oh[ob + lane + 32] = h1;
        ol[ob + lane + 32] = __float2bfloat16(acc1 - __bfloat162float(h1));
        __syncwarp();
    }
}

// ---------------- mean pool ----------------
__global__ void meanpool_kernel(const float* __restrict__ h, float* __restrict__ out) {
    const int bb = blockIdx.x;
    const int j = threadIdx.x;
    float s = 0.f;
    for (int i = 0; i < NTOK; i++) s += h[((long)bb * NTOK + i) * H_ + j];
    out[bb * H_ + j] = s * (1.f / NTOK);
}

// ---------------- host orchestration ----------------
static inline dim3 ggrid(int M, int N) { return dim3(N / 128, (M + 127) / 128); }

extern "C" void kernel_launch(void* const* d_in, const int* in_sizes, int n_in,
                              void* d_out, int out_size) {
    const float* x      = (const float*)d_in[0];
    const float* pn1_g  = (const float*)d_in[1];
    const float* pn1_b  = (const float*)d_in[2];
    const float* pW     = (const float*)d_in[3];
    const float* pb     = (const float*)d_in[4];
    const float* pn2_g  = (const float*)d_in[5];
    const float* pn2_b  = (const float*)d_in[6];
    const float* cls    = (const float*)d_in[7];
    const float* pos    = (const float*)d_in[8];
    const float* ln1_g  = (const float*)d_in[9];
    const float* ln1_b  = (const float*)d_in[10];
    const float* qkv_W  = (const float*)d_in[11];
    const float* out_W  = (const float*)d_in[12];
    const float* ln2_g  = (const float*)d_in[13];
    const float* ln2_b  = (const float*)d_in[14];
    const float* fc1_W  = (const float*)d_in[15];
    const float* fc1_b  = (const float*)d_in[16];
    const float* fc2_W  = (const float*)d_in[17];
    const float* fc2_b  = (const float*)d_in[18];
    float* out = (float*)d_out;

    float *p_h, *p_qkv, *p_tmp;
    __nv_bfloat16 *p_yh, *p_yl, *p_ahh, *p_all, *p_mh, *p_ml, *p_wh, *p_wl;
    cudaGetSymbolAddress((void**)&p_h,   g_h);
    cudaGetSymbolAddress((void**)&p_qkv, g_qkv);
    cudaGetSymbolAddress((void**)&p_tmp, g_tmp);
    cudaGetSymbolAddress((void**)&p_yh,  g_yh);
    cudaGetSymbolAddress((void**)&p_yl,  g_yl);
    cudaGetSymbolAddress((void**)&p_ahh, g_ah);
    cudaGetSymbolAddress((void**)&p_all, g_al);
    cudaGetSymbolAddress((void**)&p_mh,  g_mh);
    cudaGetSymbolAddress((void**)&p_ml,  g_ml);
    cudaGetSymbolAddress((void**)&p_wh,  g_wh);
    cudaGetSymbolAddress((void**)&p_wl,  g_wl);

    cudaFuncSetAttribute(attn_kernel, cudaFuncAttributeMaxDynamicSharedMemorySize, ATTN_SMEM_BYTES);
    cudaFuncSetAttribute(mgemm_kernel<0>, cudaFuncAttributeMaxDynamicSharedMemorySize, MG_SMEM);
    cudaFuncSetAttribute(mgemm_kernel<1>, cudaFuncAttributeMaxDynamicSharedMemorySize, MG_SMEM);
    cudaFuncSetAttribute(mgemm_kernel<2>, cudaFuncAttributeMaxDynamicSharedMemorySize, MG_SMEM);
    cudaFuncSetAttribute(mgemm_kernel<3>, cudaFuncAttributeMaxDynamicSharedMemorySize, MG_SMEM);
    cudaFuncSetAttribute(mgemm_kernel<4>, cudaFuncAttributeMaxDynamicSharedMemorySize, MG_SMEM);

    dim3 tb(32, 8);

    // 0) weight split + transpose (bf16 hi/lo, [N,K])
    wsplit_kernel<<<dim3(H_ / 32, H_ / 32), tb>>>(pW, p_wh + W_PATCH_OFF, p_wl + W_PATCH_OFF, H_, H_);
    for (int l = 0; l < L_; l++) {
        long wb = W_LAYER_BASE + (long)l * W_LAYER_SZ;
        wsplit_kernel<<<dim3(3 * H_ / 32, H_ / 32), tb>>>(qkv_W + (long)l * H_ * 3 * H_,
                                                          p_wh + wb + W_QKV_OFF, p_wl + wb + W_QKV_OFF, H_, 3 * H_);
        wsplit_kernel<<<dim3(H_ / 32, H_ / 32), tb>>>(out_W + (long)l * H_ * H_,
                                                      p_wh + wb + W_OUT_OFF, p_wl + wb + W_OUT_OFF, H_, H_);
        wsplit_kernel<<<dim3(MLP_ / 32, H_ / 32), tb>>>(fc1_W + (long)l * H_ * MLP_,
                                                        p_wh + wb + W_FC1_OFF, p_wl + wb + W_FC1_OFF, H_, MLP_);
        wsplit_kernel<<<dim3(H_ / 32, MLP_ / 32), tb>>>(fc2_W + (long)l * MLP_ * H_,
                                                        p_wh + wb + W_FC2_OFF, p_wl + wb + W_FC2_OFF, MLP_, H_);
    }

    // 1) patchify + LN(pn1)
    patchify_ln_kernel<<<PROWS, 256>>>(x, pn1_g, pn1_b, p_yh, p_yl);

    // 2) patch embed GEMM + bias -> g_tmp (f32)
    mgemm_kernel<1><<<ggrid(PROWS, H_), 256, MG_SMEM>>>(p_yh, p_yl, p_wh + W_PATCH_OFF, p_wl + W_PATCH_OFF,
                                                        pb, p_tmp, nullptr, nullptr, PROWS, H_, H_);

    // 3) LN(pn2) + cls + pos -> h
    assemble_kernel<<<ROWS, 256>>>(p_tmp, pn2_g, pn2_b, cls, pos, p_h);

    // 4) transformer layers
    for (int l = 0; l < L_; l++) {
        long wb = W_LAYER_BASE + (long)l * W_LAYER_SZ;
        const float* l1g = ln1_g + l * H_;
        const float* l1b = ln1_b + l * H_;
        const float* l2g = ln2_g + l * H_;
        const float* l2b = ln2_b + l * H_;
        const float* f1b = fc1_b + (long)l * MLP_;
        const float* f2b = fc2_b + (long)l * H_;

        ln_kernel<<<ROWS, 256>>>(p_h, p_yh, p_yl, l1g, l1b);
        mgemm_kernel<0><<<ggrid(ROWS, 3 * H_), 256, MG_SMEM>>>(p_yh, p_yl, p_wh + wb + W_QKV_OFF, p_wl + wb + W_QKV_OFF,
                                                               nullptr, p_qkv, nullptr, nullptr, ROWS, 3 * H_, H_);
        attn_kernel<<<B_ * NH, 256, ATTN_SMEM_BYTES>>>(p_qkv, p_ahh, p_all);
        mgemm_kernel<4><<<ggrid(ROWS, H_), 256, MG_SMEM>>>(p_ahh, p_all, p_wh + wb + W_OUT_OFF, p_wl + wb + W_OUT_OFF,
                                                           nullptr, p_h, nullptr, nullptr, ROWS, H_, H_);
        ln_kernel<<<ROWS, 256>>>(p_h, p_yh, p_yl, l2g, l2b);
        mgemm_kernel<2><<<ggrid(ROWS, MLP_), 256, MG_SMEM>>>(p_yh, p_yl, p_wh + wb + W_FC1_OFF, p_wl + wb + W_FC1_OFF,
                                                             f1b, nullptr, p_mh, p_ml, ROWS, MLP_, H_);
        mgemm_kernel<3><<<ggrid(ROWS, H_), 256, MG_SMEM>>>(p_mh, p_ml, p_wh + wb + W_FC2_OFF, p_wl + wb + W_FC2_OFF,
                                                           f2b, p_h, nullptr, nullptr, ROWS, H_, MLP_);
    }

    // 5) mean pool
    meanpool_kernel<<<B_, H_>>>(p_h, out);
}

// round 5
// speedup vs baseline: 2.6945x; 1.0124x over previous
#include <cuda_runtime.h>
#include <cuda_bf16.h>
#include <math.h>
#include <cstdint>

// ---------------- problem constants ----------------
static constexpr int B_   = 32;
static constexpr int CCH  = 3;
static constexpr int IMG  = 224;
static constexpr int P_   = 16;
static constexpr int GRD  = IMG / P_;        // 14
static constexpr int NP   = GRD * GRD;       // 196
static constexpr int NTOK = NP + 1;          // 197
static constexpr int H_   = 768;
static constexpr int NH   = 12;
static constexpr int HD   = 64;
static constexpr int MLP_ = 3072;
static constexpr int L_   = 12;
static constexpr int ROWS = B_ * NTOK;       // 6304
static constexpr int PROWS = B_ * NP;        // 6272

// weight scratch layout (bf16 hi/lo, transposed to [N,K])
static constexpr long W_PATCH_OFF = 0;                       // 768x768
static constexpr long W_LAYER_BASE = 768L * 768;
static constexpr long W_LAYER_SZ   = 768L*2304 + 768L*768 + 768L*3072 + 3072L*768;
static constexpr long W_QKV_OFF = 0;
static constexpr long W_OUT_OFF = 768L*2304;
static constexpr long W_FC1_OFF = W_OUT_OFF + 768L*768;
static constexpr long W_FC2_OFF = W_FC1_OFF + 768L*3072;
static constexpr long W_TOTAL = W_LAYER_BASE + 12L * W_LAYER_SZ;

// ---------------- device scratch ----------------
__device__ float g_h   [ROWS * H_];
__device__ float g_qkv [ROWS * 3 * H_];
__device__ float g_tmp [PROWS * H_];
__device__ __align__(256) __nv_bfloat16 g_yh [ROWS * H_];
__device__ __align__(256) __nv_bfloat16 g_yl [ROWS * H_];
__device__ __align__(256) __nv_bfloat16 g_ah [ROWS * H_];
__device__ __align__(256) __nv_bfloat16 g_al [ROWS * H_];
__device__ __align__(256) __nv_bfloat16 g_mh [ROWS * MLP_];
__device__ __align__(256) __nv_bfloat16 g_ml [ROWS * MLP_];
__device__ __align__(256) __nv_bfloat16 g_wh [W_TOTAL];
__device__ __align__(256) __nv_bfloat16 g_wl [W_TOTAL];

// ---------------- helpers ----------------
__device__ __forceinline__ uint32_t smem_u32(const void* p) {
    uint32_t a;
    asm("{ .reg .u64 t; cvta.to.shared.u64 t, %1; cvt.u32.u64 %0, t; }" : "=r"(a) : "l"(p));
    return a;
}
__device__ __forceinline__ void cp16(uint32_t dst, const void* src, bool valid) {
    int sz = valid ? 16 : 0;
    asm volatile("cp.async.cg.shared.global [%0], [%1], 16, %2;"
                 :: "r"(dst), "l"(src), "r"(sz) : "memory");
}
__device__ __forceinline__ void cp_commit() {
    asm volatile("cp.async.commit_group;" ::: "memory");
}
__device__ __forceinline__ void cp_wait1() {
    asm volatile("cp.async.wait_group 1;" ::: "memory");
}
__device__ __forceinline__ void ldm4(uint32_t* r, uint32_t addr) {
    asm volatile("ldmatrix.sync.aligned.m8n8.x4.shared.b16 {%0,%1,%2,%3}, [%4];"
                 : "=r"(r[0]), "=r"(r[1]), "=r"(r[2]), "=r"(r[3]) : "r"(addr));
}
__device__ __forceinline__ void mma_bf16(float* d, const uint32_t* a, uint32_t b0, uint32_t b1) {
    asm volatile(
        "mma.sync.aligned.m16n8k16.row.col.f32.bf16.bf16.f32 "
        "{%0,%1,%2,%3}, {%4,%5,%6,%7}, {%8,%9}, {%0,%1,%2,%3};"
        : "+f"(d[0]), "+f"(d[1]), "+f"(d[2]), "+f"(d[3])
        : "r"(a[0]), "r"(a[1]), "r"(a[2]), "r"(a[3]), "r"(b0), "r"(b1));
}
__device__ __forceinline__ float gelu_exact(float x) {
    return 0.5f * x * (1.0f + erff(x * 0.70710678118654752f));
}

// ---------------- mega weight split+transpose (all weights, one launch) ----------------
// For each segment: W[K,N] f32 -> Wh/Wl[N,K] bf16
__global__ void wsplit_mega_kernel(const float* __restrict__ pW,
                                   const float* __restrict__ qkvW,
                                   const float* __restrict__ outW,
                                   const float* __restrict__ fc1W,
                                   const float* __restrict__ fc2W,
                                   __nv_bfloat16* __restrict__ GWh,
                                   __nv_bfloat16* __restrict__ GWl) {
    const int seg = blockIdx.y;       // 0..48
    int K, N;
    const float* src;
    long dstoff;
    if (seg == 0) {
        K = 768; N = 768; src = pW; dstoff = W_PATCH_OFF;
    } else {
        int t = (seg - 1) & 3, l = (seg - 1) >> 2;
        long wb = W_LAYER_BASE + (long)l * W_LAYER_SZ;
        if (t == 0)      { K = 768;  N = 2304; src = qkvW + (long)l * 768 * 2304; dstoff = wb + W_QKV_OFF; }
        else if (t == 1) { K = 768;  N = 768;  src = outW + (long)l * 768 * 768;  dstoff = wb + W_OUT_OFF; }
        else if (t == 2) { K = 768;  N = 3072; src = fc1W + (long)l * 768 * 3072; dstoff = wb + W_FC1_OFF; }
        else             { K = 3072; N = 768;  src = fc2W + (long)l * 3072 * 768; dstoff = wb + W_FC2_OFF; }
    }
    const int tn = N >> 5, tk = K >> 5;
    const int tile = blockIdx.x;
    if (tile >= tn * tk) return;
    const int n0 = (tile % tn) * 32, k0 = (tile / tn) * 32;

    __shared__ float t_[32][33];
    const int tx = threadIdx.x, ty = threadIdx.y;    // 32 x 8
    #pragma unroll
    for (int i = 0; i < 32; i += 8)
        t_[ty + i][tx] = src[(long)(k0 + ty + i) * N + n0 + tx];
    __syncthreads();
    __nv_bfloat16* Wh = GWh + dstoff;
    __nv_bfloat16* Wl = GWl + dstoff;
    #pragma unroll
    for (int i = 0; i < 32; i += 8) {
        float v = t_[tx][ty + i];
        long o = (long)(n0 + ty + i) * K + k0 + tx;
        __nv_bfloat16 h = __float2bfloat16(v);
        Wh[o] = h;
        Wl[o] = __float2bfloat16(v - __bfloat162float(h));
    }
}

// ---------------- tensor-core GEMM via mma.sync (bf16 hi/lo split) ----------------
// C[M,N] = (Ah+Al)[M,K] @ (Wh+Wl)^T[N,K], fp32 accum.
// EPI: 0 store f32 | 1 +bias f32 | 2 +bias,gelu -> bf16 hi/lo | 3 +bias,gelu,+=C | 4 +=C
static constexpr int MG_STAGE = 32768;            // 4 tiles x 8KB
static constexpr int MG_SMEM  = 3 * MG_STAGE;     // 98304

template<int EPI>
__global__ void __launch_bounds__(256, 2) mgemm_kernel(
    const __nv_bfloat16* __restrict__ Ah, const __nv_bfloat16* __restrict__ Al,
    const __nv_bfloat16* __restrict__ Wh, const __nv_bfloat16* __restrict__ Wl,
    const float* __restrict__ bias, float* __restrict__ C,
    __nv_bfloat16* __restrict__ Oh, __nv_bfloat16* __restrict__ Ol,
    int M, int N, int K)
{
    extern __shared__ char smc[];
    const uint32_t smb = smem_u32(smc);
    const int tid = threadIdx.x;
    const int lane = tid & 31, warp = tid >> 5;
    const int wm = warp >> 1, wn = warp & 1;      // 4 x 2 warp grid
    const int n0 = blockIdx.x * 128, m0 = blockIdx.y * 128;
    const int KT = K >> 5;

    float acc[2][8][4];
    #pragma unroll
    for (int a = 0; a < 2; a++)
        #pragma unroll
        for (int b = 0; b < 8; b++)
            #pragma unroll
            for (int c = 0; c < 4; c++) acc[a][b][c] = 0.f;

    auto issue = [&](int kt, int s) {
        const int k0 = kt << 5;
        const uint32_t st = smb + s * MG_STAGE;
        #pragma unroll
        for (int i = 0; i < 2; i++) {
            int idx = tid + (i << 8);
            int row = idx >> 2, ch = idx & 3;
            uint32_t off = (uint32_t)(row * 64 + ((ch ^ ((row >> 1) & 3)) << 4));
            bool av = (m0 + row) < M;
            long aoff = (long)(m0 + row) * K + k0 + ch * 8;
            long boff = (long)(n0 + row) * K + k0 + ch * 8;
            cp16(st +      0 + off, Ah + aoff, av);
            cp16(st +  8192 + off, Al + aoff, av);
            cp16(st + 16384 + off, Wh + boff, true);
            cp16(st + 24576 + off, Wl + boff, true);
        }
    };
    auto ldaddr = [&](uint32_t tb, int r0, int ks) -> uint32_t {
        int row = r0 + (lane & 7) + ((lane & 8) ? 8 : 0);
        int ch  = (ks << 1) + ((lane >> 4) & 1);
        return tb + (uint32_t)(row * 64 + ((ch ^ ((row >> 1) & 3)) << 4));
    };

    issue(0, 0);
    cp_commit();
    if (KT > 1) issue(1, 1);
    cp_commit();

    for (int kt = 0; kt < KT; kt++) {
        cp_wait1();
        __syncthreads();
        int pf = kt + 2;
        if (pf < KT) issue(pf, pf % 3);
        cp_commit();

        const uint32_t st = smb + (kt % 3) * MG_STAGE;
        #pragma unroll
        for (int ks = 0; ks < 2; ks++) {
            uint32_t ah[2][4], al[2][4];
            #pragma unroll
            for (int mt = 0; mt < 2; mt++) {
                ldm4(ah[mt], ldaddr(st +    0, wm * 32 + mt * 16, ks));
                ldm4(al[mt], ldaddr(st + 8192, wm * 32 + mt * 16, ks));
            }
            #pragma unroll
            for (int g = 0; g < 4; g++) {
                uint32_t bh[4], bl[4];
                ldm4(bh, ldaddr(st + 16384, wn * 64 + g * 16, ks));
                ldm4(bl, ldaddr(st + 24576, wn * 64 + g * 16, ks));
                #pragma unroll
                for (int mt = 0; mt < 2; mt++)
                    #pragma unroll
                    for (int sl = 0; sl < 2; sl++) {
                        int nt = g * 2 + sl;
                        mma_bf16(acc[mt][nt], ah[mt], bh[sl], bh[sl + 2]);
                        mma_bf16(acc[mt][nt], ah[mt], bl[sl], bl[sl + 2]);
                        mma_bf16(acc[mt][nt], al[mt], bh[sl], bh[sl + 2]);
                    }
            }
        }
    }

    // epilogue
    #pragma unroll
    for (int mt = 0; mt < 2; mt++)
        #pragma unroll
        for (int nt = 0; nt < 8; nt++) {
            int cb = n0 + wn * 64 + nt * 8 + (lane & 3) * 2;
            #pragma unroll
            for (int h = 0; h < 2; h++) {
                int r = m0 + wm * 32 + mt * 16 + (lane >> 2) + h * 8;
                if (r < M) {
                    float v0 = acc[mt][nt][h * 2 + 0];
                    float v1 = acc[mt][nt][h * 2 + 1];
                    if (EPI == 1 || EPI == 2 || EPI == 3) { v0 += bias[cb]; v1 += bias[cb + 1]; }
                    if (EPI == 2 || EPI == 3) { v0 = gelu_exact(v0); v1 = gelu_exact(v1); }
                    if (EPI == 2) {
                        long o = (long)r * N + cb;
                        __nv_bfloat16 h0 = __float2bfloat16(v0);
                        __nv_bfloat16 h1 = __float2bfloat16(v1);
                        Oh[o] = h0;      Ol[o] = __float2bfloat16(v0 - __bfloat162float(h0));
                        Oh[o + 1] = h1;  Ol[o + 1] = __float2bfloat16(v1 - __bfloat162float(h1));
                    } else {
                        float* cp = C + (long)r * N + cb;
                        if (EPI == 3 || EPI == 4) { v0 += cp[0]; v1 += cp[1]; }
                        cp[0] = v0; cp[1] = v1;
                    }
                }
            }
        }
}

// ---------------- LayerNorm (768) -> bf16 hi/lo ----------------
__global__ void ln_kernel(const float* __restrict__ in, __nv_bfloat16* __restrict__ yh,
                          __nv_bfloat16* __restrict__ yl,
                          const float* __restrict__ g, const float* __restrict__ b) {
    const int row = blockIdx.x;
    const int tid = threadIdx.x;  // 256
    const float* x = in + (long)row * H_;
    float v0 = x[tid], v1 = x[tid + 256], v2 = x[tid + 512];
    __shared__ float red[256];
    __shared__ float s_mean, s_rstd;
    red[tid] = v0 + v1 + v2;
    __syncthreads();
    for (int o = 128; o > 0; o >>= 1) { if (tid < o) red[tid] += red[tid + o]; __syncthreads(); }
    if (tid == 0) s_mean = red[0] * (1.f / H_);
    __syncthreads();
    float m = s_mean;
    float d0 = v0 - m, d1 = v1 - m, d2 = v2 - m;
    red[tid] = d0 * d0 + d1 * d1 + d2 * d2;
    __syncthreads();
    for (int o = 128; o > 0; o >>= 1) { if (tid < o) red[tid] += red[tid + o]; __syncthreads(); }
    if (tid == 0) s_rstd = rsqrtf(red[0] * (1.f / H_) + 1e-5f);
    __syncthreads();
    float rs = s_rstd;
    long base = (long)row * H_;
    #pragma unroll
    for (int rr = 0; rr < 3; rr++) {
        int c = tid + rr * 256;
        float d = (rr == 0 ? d0 : rr == 1 ? d1 : d2);
        float v = d * rs * g[c] + b[c];
        __nv_bfloat16 h = __float2bfloat16(v);
        yh[base + c] = h;
        yl[base + c] = __float2bfloat16(v - __bfloat162float(h));
    }
}

// ---------------- patchify + LN(pn1) -> bf16 hi/lo ----------------
__global__ void patchify_ln_kernel(const float* __restrict__ x,
                                   const float* __restrict__ g, const float* __restrict__ b,
                                   __nv_bfloat16* __restrict__ yh, __nv_bfloat16* __restrict__ yl) {
    const int pidx = blockIdx.x;
    const int bimg = pidx / NP;
    const int pp   = pidx % NP;
    const int hg = pp / GRD, wg = pp % GRD;
    const int tid = threadIdx.x;
    float v[3];
    #pragma unroll
    for (int r = 0; r < 3; r++) {
        int f = tid + r * 256;
        int p1 = f / 48, rem = f % 48, p2 = rem / 3, c = rem % 3;
        v[r] = x[(((long)bimg * CCH + c) * IMG + (hg * P_ + p1)) * IMG + (wg * P_ + p2)];
    }
    __shared__ float red[256];
    __shared__ float s_mean, s_rstd;
    red[tid] = v[0] + v[1] + v[2];
    __syncthreads();
    for (int o = 128; o > 0; o >>= 1) { if (tid < o) red[tid] += red[tid + o]; __syncthreads(); }
    if (tid == 0) s_mean = red[0] * (1.f / H_);
    __syncthreads();
    float m = s_mean;
    float d0 = v[0] - m, d1 = v[1] - m, d2 = v[2] - m;
    red[tid] = d0 * d0 + d1 * d1 + d2 * d2;
    __syncthreads();
    for (int o = 128; o > 0; o >>= 1) { if (tid < o) red[tid] += red[tid + o]; __syncthreads(); }
    if (tid == 0) s_rstd = rsqrtf(red[0] * (1.f / H_) + 1e-5f);
    __syncthreads();
    float rs = s_rstd;
    long base = (long)pidx * H_;
    #pragma unroll
    for (int rr = 0; rr < 3; rr++) {
        int c = tid + rr * 256;
        float d = (rr == 0 ? d0 : rr == 1 ? d1 : d2);
        float vv = d * rs * g[c] + b[c];
        __nv_bfloat16 h = __float2bfloat16(vv);
        yh[base + c] = h;
        yl[base + c] = __float2bfloat16(vv - __bfloat162float(h));
    }
}

// ---------------- LN(pn2) + cls + pos -> h (f32) ----------------
__global__ void assemble_kernel(const float* __restrict__ pemb,
                                const float* __restrict__ g, const float* __restrict__ b,
                                const float* __restrict__ cls, const float* __restrict__ pos,
                                float* __restrict__ h) {
    const int row = blockIdx.x;
    const int bb = row / NTOK, t = row % NTOK;
    const int tid = threadIdx.x;
    float* o_ = h + (long)row * H_;
    if (t == 0) {
        o_[tid]       = cls[tid]       + pos[tid];
        o_[tid + 256] = cls[tid + 256] + pos[tid + 256];
        o_[tid + 512] = cls[tid + 512] + pos[tid + 512];
        return;
    }
    const float* x = pemb + (long)(bb * NP + t - 1) * H_;
    float v0 = x[tid], v1 = x[tid + 256], v2 = x[tid + 512];
    __shared__ float red[256];
    __shared__ float s_mean, s_rstd;
    red[tid] = v0 + v1 + v2;
    __syncthreads();
    for (int o = 128; o > 0; o >>= 1) { if (tid < o) red[tid] += red[tid + o]; __syncthreads(); }
    if (tid == 0) s_mean = red[0] * (1.f / H_);
    __syncthreads();
    float m = s_mean;
    float d0 = v0 - m, d1 = v1 - m, d2 = v2 - m;
    red[tid] = d0 * d0 + d1 * d1 + d2 * d2;
    __syncthreads();
    for (int o = 128; o > 0; o >>= 1) { if (tid < o) red[tid] += red[tid + o]; __syncthreads(); }
    if (tid == 0) s_rstd = rsqrtf(red[0] * (1.f / H_) + 1e-5f);
    __syncthreads();
    float rs = s_rstd;
    const float* pp = pos + (long)t * H_;
    o_[tid]       = d0 * rs * g[tid]       + b[tid]       + pp[tid];
    o_[tid + 256] = d1 * rs * g[tid + 256] + b[tid + 256] + pp[tid + 256];
    o_[tid + 512] = d2 * rs * g[tid + 512] + b[tid + 512] + pp[tid + 512];
}

// ---------------- attention: one block per (batch, head); out bf16 hi/lo ----------------
static constexpr int KSTR = HD + 1;           // 65
static constexpr int ATTN_SMEM_FLOATS = NTOK * KSTR + NTOK * HD + 8 * 224 + 8 * HD;
static constexpr int ATTN_SMEM_BYTES  = ATTN_SMEM_FLOATS * 4;

__global__ void attn_kernel(const float* __restrict__ qkv,
                            __nv_bfloat16* __restrict__ oh, __nv_bfloat16* __restrict__ ol) {
    extern __shared__ float smf[];
    float* Ks    = smf;
    float* Vs    = Ks + NTOK * KSTR;
    float* Srows = Vs + NTOK * HD;
    float* Qrows = Srows + 8 * 224;

    const int bh = blockIdx.x;
    const int bb = bh / NH, head = bh % NH;
    const int tid = threadIdx.x, lane = tid & 31, warp = tid >> 5;
    const float* base = qkv + (long)bb * NTOK * 3 * H_;
    const int hoff = head * HD;

    for (int idx = tid; idx < NTOK * HD; idx += 256) {
        int j = idx / HD, d = idx % HD;
        const float* r = base + (long)j * 3 * H_;
        Ks[j * KSTR + d] = r[H_ + hoff + d];
        Vs[j * HD + d]   = r[2 * H_ + hoff + d];
    }
    __syncthreads();

    float* srow = Srows + warp * 224;
    float* qrow = Qrows + warp * HD;

    for (int i = warp; i < NTOK; i += 8) {
        const float* qr = base + (long)i * 3 * H_ + hoff;
        qrow[lane]      = qr[lane];
        qrow[lane + 32] = qr[lane + 32];
        __syncwarp();
        float lmax = -1e30f;
        for (int j = lane; j < NTOK; j += 32) {
            float dot = 0.f;
            #pragma unroll
            for (int d = 0; d < HD; d++) dot += qrow[d] * Ks[j * KSTR + d];
            dot *= 0.125f;
            srow[j] = dot;
            lmax = fmaxf(lmax, dot);
        }
        #pragma unroll
        for (int o = 16; o > 0; o >>= 1) lmax = fmaxf(lmax, __shfl_xor_sync(0xffffffffu, lmax, o));
        __syncwarp();
        float lsum = 0.f;
        for (int j = lane; j < NTOK; j += 32) {
            float e = __expf(srow[j] - lmax);
            srow[j] = e;
            lsum += e;
        }
        #pragma unroll
        for (int o = 16; o > 0; o >>= 1) lsum += __shfl_xor_sync(0xffffffffu, lsum, o);
        float inv = 1.f / lsum;
        __syncwarp();
        float acc0 = 0.f, acc1 = 0.f;
        for (int j = 0; j < NTOK; j++) {
            float w = srow[j];
            acc0 += w * Vs[j * HD + lane];
            acc1 += w * Vs[j * HD + lane + 32];
        }
        acc0 *= inv; acc1 *= inv;
        long ob = (long)(bb * NTOK + i) * H_ + hoff;
        __nv_bfloat16 h0 = __float2bfloat16(acc0);
        __nv_bfloat16 h1 = __float2bfloat16(acc1);
        oh[ob + lane]      = h0;
        ol[ob + lane]      = __float2bfloat16(acc0 - __bfloat162float(h0));
        oh[ob + lane + 32] = h1;
        ol[ob + lane + 32] = __float2bfloat16(acc1 - __bfloat162float(h1));
        __syncwarp();
    }
}

// ---------------- mean pool ----------------
__global__ void meanpool_kernel(const float* __restrict__ h, float* __restrict__ out) {
    const int bb = blockIdx.x;
    const int j = threadIdx.x;
    float s = 0.f;
    for (int i = 0; i < NTOK; i++) s += h[((long)bb * NTOK + i) * H_ + j];
    out[bb * H_ + j] = s * (1.f / NTOK);
}

// ---------------- host orchestration ----------------
static inline dim3 ggrid(int M, int N) { return dim3(N / 128, (M + 127) / 128); }

extern "C" void kernel_launch(void* const* d_in, const int* in_sizes, int n_in,
                              void* d_out, int out_size) {
    const float* x      = (const float*)d_in[0];
    const float* pn1_g  = (const float*)d_in[1];
    const float* pn1_b  = (const float*)d_in[2];
    const float* pW     = (const float*)d_in[3];
    const float* pb     = (const float*)d_in[4];
    const float* pn2_g  = (const float*)d_in[5];
    const float* pn2_b  = (const float*)d_in[6];
    const float* cls    = (const float*)d_in[7];
    const float* pos    = (const float*)d_in[8];
    const float* ln1_g  = (const float*)d_in[9];
    const float* ln1_b  = (const float*)d_in[10];
    const float* qkv_W  = (const float*)d_in[11];
    const float* out_W  = (const float*)d_in[12];
    const float* ln2_g  = (const float*)d_in[13];
    const float* ln2_b  = (const float*)d_in[14];
    const float* fc1_W  = (const float*)d_in[15];
    const float* fc1_b  = (const float*)d_in[16];
    const float* fc2_W  = (const float*)d_in[17];
    const float* fc2_b  = (const float*)d_in[18];
    float* out = (float*)d_out;

    float *p_h, *p_qkv, *p_tmp;
    __nv_bfloat16 *p_yh, *p_yl, *p_ahh, *p_all, *p_mh, *p_ml, *p_wh, *p_wl;
    cudaGetSymbolAddress((void**)&p_h,   g_h);
    cudaGetSymbolAddress((void**)&p_qkv, g_qkv);
    cudaGetSymbolAddress((void**)&p_tmp, g_tmp);
    cudaGetSymbolAddress((void**)&p_yh,  g_yh);
    cudaGetSymbolAddress((void**)&p_yl,  g_yl);
    cudaGetSymbolAddress((void**)&p_ahh, g_ah);
    cudaGetSymbolAddress((void**)&p_all, g_al);
    cudaGetSymbolAddress((void**)&p_mh,  g_mh);
    cudaGetSymbolAddress((void**)&p_ml,  g_ml);
    cudaGetSymbolAddress((void**)&p_wh,  g_wh);
    cudaGetSymbolAddress((void**)&p_wl,  g_wl);

    cudaFuncSetAttribute(attn_kernel, cudaFuncAttributeMaxDynamicSharedMemorySize, ATTN_SMEM_BYTES);
    cudaFuncSetAttribute(mgemm_kernel<0>, cudaFuncAttributeMaxDynamicSharedMemorySize, MG_SMEM);
    cudaFuncSetAttribute(mgemm_kernel<1>, cudaFuncAttributeMaxDynamicSharedMemorySize, MG_SMEM);
    cudaFuncSetAttribute(mgemm_kernel<2>, cudaFuncAttributeMaxDynamicSharedMemorySize, MG_SMEM);
    cudaFuncSetAttribute(mgemm_kernel<3>, cudaFuncAttributeMaxDynamicSharedMemorySize, MG_SMEM);
    cudaFuncSetAttribute(mgemm_kernel<4>, cudaFuncAttributeMaxDynamicSharedMemorySize, MG_SMEM);

    // 0) mega weight split (1 launch, all 49 weight matrices)
    wsplit_mega_kernel<<<dim3(2304, 49), dim3(32, 8)>>>(pW, qkv_W, out_W, fc1_W, fc2_W, p_wh, p_wl);

    // 1) patchify + LN(pn1)
    patchify_ln_kernel<<<PROWS, 256>>>(x, pn1_g, pn1_b, p_yh, p_yl);

    // 2) patch embed GEMM + bias -> g_tmp (f32)
    mgemm_kernel<1><<<ggrid(PROWS, H_), 256, MG_SMEM>>>(p_yh, p_yl, p_wh + W_PATCH_OFF, p_wl + W_PATCH_OFF,
                                                        pb, p_tmp, nullptr, nullptr, PROWS, H_, H_);

    // 3) LN(pn2) + cls + pos -> h
    assemble_kernel<<<ROWS, 256>>>(p_tmp, pn2_g, pn2_b, cls, pos, p_h);

    // 4) transformer layers  (launch #5 = ln, #6 = QKV mgemm -> ncu -s 5 captures the GEMM)
    for (int l = 0; l < L_; l++) {
        long wb = W_LAYER_BASE + (long)l * W_LAYER_SZ;
        const float* l1g = ln1_g + l * H_;
        const float* l1b = ln1_b + l * H_;
        const float* l2g = ln2_g + l * H_;
        const float* l2b = ln2_b + l * H_;
        const float* f1b = fc1_b + (long)l * MLP_;
        const float* f2b = fc2_b + (long)l * H_;

        ln_kernel<<<ROWS, 256>>>(p_h, p_yh, p_yl, l1g, l1b);
        mgemm_kernel<0><<<ggrid(ROWS, 3 * H_), 256, MG_SMEM>>>(p_yh, p_yl, p_wh + wb + W_QKV_OFF, p_wl + wb + W_QKV_OFF,
                                                               nullptr, p_qkv, nullptr, nullptr, ROWS, 3 * H_, H_);
        attn_kernel<<<B_ * NH, 256, ATTN_SMEM_BYTES>>>(p_qkv, p_ahh, p_all);
        mgemm_kernel<4><<<ggrid(ROWS, H_), 256, MG_SMEM>>>(p_ahh, p_all, p_wh + wb + W_OUT_OFF, p_wl + wb + W_OUT_OFF,
                                                           nullptr, p_h, nullptr, nullptr, ROWS, H_, H_);
        ln_kernel<<<ROWS, 256>>>(p_h, p_yh, p_yl, l2g, l2b);
        mgemm_kernel<2><<<ggrid(ROWS, MLP_), 256, MG_SMEM>>>(p_yh, p_yl, p_wh + wb + W_FC1_OFF, p_wl + wb + W_FC1_OFF,
                                                             f1b, nullptr, p_mh, p_ml, ROWS, MLP_, H_);
        mgemm_kernel<3><<<ggrid(ROWS, H_), 256, MG_SMEM>>>(p_mh, p_ml, p_wh + wb + W_FC2_OFF, p_wl + wb + W_FC2_OFF,
                                                           f2b, p_h, nullptr, nullptr, ROWS, H_, MLP_);
    }

    // 5) mean pool
    meanpool_kernel<<<B_, H_>>>(p_h, out);
}